// round 8
// baseline (speedup 1.0000x reference)
#include <cuda_runtime.h>
#include <math.h>

// ---------------- problem constants ----------------
constexpr int kB   = 8;
constexpr int kN   = 2048;
constexpr int kM   = 512;
constexpr int kCIN = 256;
constexpr int kCFP = 128;
constexpr int kC   = 128;   // C_OUT
constexpr int kCG  = 512;
constexpr int kH   = 8;
constexpr int kD   = 16;    // head dim

// ---------------- scratch (no allocation allowed) ----------------
__device__ float g_interp[kB * kCIN * kN];
__device__ float g_h1    [kB * kCIN * kN];
__device__ float g_nf    [kB * kCFP * kN];
__device__ float g_qf    [kB * kC   * kN];
__device__ float g_vf    [kB * kC   * kN];
__device__ float g_Q     [kB * kC   * kN];
__device__ float g_K     [kB * kC   * kN];
__device__ float g_V     [kB * kC   * kN];
__device__ float g_O     [kB * kC   * kN];
__device__ float g_y     [kB * kC   * kN];
__device__ float g_gb    [kB * kC];
__device__ int   g_idx   [kB * kN * 3];
__device__ float g_w     [kB * kN * 3];

// ---------------- tf32 / tensor helpers ----------------
__device__ __forceinline__ float ex2(float x) {
    float y;
    asm("ex2.approx.f32 %0, %1;" : "=f"(y) : "f"(x));
    return y;
}
__device__ __forceinline__ unsigned cvt_tf32(float f) {
    unsigned u;
    asm("cvt.rna.tf32.f32 %0, %1;" : "=r"(u) : "f"(f));
    return u;
}
// D = A(16x8,row) * B(8x8,col) + D, tf32 in, fp32 accum
__device__ __forceinline__ void mma_tf32(float c[4], const unsigned a[4],
                                         unsigned b0, unsigned b1) {
    asm volatile(
        "mma.sync.aligned.m16n8k8.row.col.f32.tf32.tf32.f32 "
        "{%0,%1,%2,%3}, {%4,%5,%6,%7}, {%8,%9}, {%0,%1,%2,%3};"
        : "+f"(c[0]), "+f"(c[1]), "+f"(c[2]), "+f"(c[3])
        : "r"(a[0]), "r"(a[1]), "r"(a[2]), "r"(a[3]), "r"(b0), "r"(b1));
}
__device__ __forceinline__ float2 split2(float x) {
    const unsigned hi = cvt_tf32(x);
    const float hf = __uint_as_float(hi);
    return make_float2(hf, x - hf);     // lo kept as f32; MMA unit truncates
}

// ---------------- three_nn ----------------
__global__ __launch_bounds__(128) void knn_kernel(
    const float* __restrict__ up_xyz, const float* __restrict__ xyz,
    int* __restrict__ idxo, float* __restrict__ wo)
{
    __shared__ float sx[kM * 3];
    const int b = blockIdx.y;
    for (int i = threadIdx.x; i < kM * 3; i += 128) sx[i] = xyz[b * kM * 3 + i];
    __syncthreads();

    const int n = blockIdx.x * 128 + threadIdx.x;
    const float px = up_xyz[(b * kN + n) * 3 + 0];
    const float py = up_xyz[(b * kN + n) * 3 + 1];
    const float pz = up_xyz[(b * kN + n) * 3 + 2];

    float d0 = 1e30f, d1 = 1e30f, d2 = 1e30f;
    int   i0 = 0,     i1 = 0,     i2 = 0;
    for (int m = 0; m < kM; m++) {
        float dx = sx[m * 3 + 0] - px;
        float dy = sx[m * 3 + 1] - py;
        float dz = sx[m * 3 + 2] - pz;
        float d  = dx * dx + dy * dy + dz * dz;
        if (d < d2) {
            if (d < d1) {
                if (d < d0) { d2 = d1; i2 = i1; d1 = d0; i1 = i0; d0 = d; i0 = m; }
                else        { d2 = d1; i2 = i1; d1 = d;  i1 = m; }
            } else          { d2 = d;  i2 = m; }
        }
    }
    d0 = fmaxf(d0, 1e-10f); d1 = fmaxf(d1, 1e-10f); d2 = fmaxf(d2, 1e-10f);
    float r0 = 1.0f / d0, r1 = 1.0f / d1, r2 = 1.0f / d2;
    float s  = r0 + r1 + r2;
    const int base = (b * kN + n) * 3;
    idxo[base] = i0; idxo[base + 1] = i1; idxo[base + 2] = i2;
    wo[base] = r0 / s; wo[base + 1] = r1 / s; wo[base + 2] = r2 / s;
}

// ---------------- inverse-distance interpolation ----------------
__global__ void interp_kernel(
    const float* __restrict__ feat, const int* __restrict__ idx3,
    const float* __restrict__ w3, float* __restrict__ out)
{
    const int b = blockIdx.z, c = blockIdx.y;
    const int n = blockIdx.x * 256 + threadIdx.x;
    const float* f = feat + ((size_t)b * kCIN + c) * kM;
    const int base = (b * kN + n) * 3;
    const int j0 = idx3[base], j1 = idx3[base + 1], j2 = idx3[base + 2];
    const float w0 = w3[base], w1 = w3[base + 1], w2 = w3[base + 2];
    out[((size_t)b * kCIN + c) * kN + n] = w0 * f[j0] + w1 * f[j1] + w2 * f[j2];
}

// ---------------- 3xTF32 GEMM, hi/lo pre-split in smem ----------------
// 128oc x 128n tile, 256 threads, warp w: oc (w&3)*32, n (w>>2)*64.
__device__ __forceinline__ void gemm_mma_tile(
    const float* __restrict__ W, const float* __restrict__ Xb, float* __restrict__ Yb,
    int IC, int n0,
    const float* bias, const float* gamma, const float* beta,
    const float* addB, int relu,
    float2 (*Ws)[132], float2 (*Xs)[132])
{
    const int tid  = threadIdx.x;
    const int w    = tid >> 5;
    const int lane = tid & 31;
    const int g    = lane >> 2;
    const int t    = lane & 3;
    const int ocw  = (w & 3) * 32;
    const int nw   = (w >> 2) * 64;

    // loaders
    const int ocl = tid >> 1, kq = (tid & 1) * 8;      // W: 8 elems/thread
    const int kx  = tid >> 4, nx = (tid & 15) * 8;     // X: 8 elems/thread

    float c[2][8][4];
#pragma unroll
    for (int i = 0; i < 2; i++)
#pragma unroll
        for (int j = 0; j < 8; j++)
#pragma unroll
            for (int r = 0; r < 4; r++) c[i][j][r] = 0.0f;

    for (int k0 = 0; k0 < IC; k0 += 16) {
        const float4 wa = *(const float4*)&W[(size_t)ocl * IC + k0 + kq];
        const float4 wb = *(const float4*)&W[(size_t)ocl * IC + k0 + kq + 4];
        const float4 xa = *(const float4*)&Xb[(size_t)(k0 + kx) * kN + n0 + nx];
        const float4 xb = *(const float4*)&Xb[(size_t)(k0 + kx) * kN + n0 + nx + 4];
        __syncthreads();
        Ws[kq + 0][ocl] = split2(wa.x); Ws[kq + 1][ocl] = split2(wa.y);
        Ws[kq + 2][ocl] = split2(wa.z); Ws[kq + 3][ocl] = split2(wa.w);
        Ws[kq + 4][ocl] = split2(wb.x); Ws[kq + 5][ocl] = split2(wb.y);
        Ws[kq + 6][ocl] = split2(wb.z); Ws[kq + 7][ocl] = split2(wb.w);
        Xs[kx][nx + 0] = split2(xa.x); Xs[kx][nx + 1] = split2(xa.y);
        Xs[kx][nx + 2] = split2(xa.z); Xs[kx][nx + 3] = split2(xa.w);
        Xs[kx][nx + 4] = split2(xb.x); Xs[kx][nx + 5] = split2(xb.y);
        Xs[kx][nx + 6] = split2(xb.z); Xs[kx][nx + 7] = split2(xb.w);
        __syncthreads();

#pragma unroll
        for (int ks = 0; ks < 2; ks++) {
            const int r0 = ks * 8 + t, r1 = ks * 8 + t + 4;
            unsigned ahi[2][4], alo[2][4];
#pragma unroll
            for (int i = 0; i < 2; i++) {
                const int oc = ocw + i * 16 + g;
                const float2 a0 = Ws[r0][oc];
                const float2 a1 = Ws[r0][oc + 8];
                const float2 a2 = Ws[r1][oc];
                const float2 a3 = Ws[r1][oc + 8];
                ahi[i][0] = __float_as_uint(a0.x); alo[i][0] = __float_as_uint(a0.y);
                ahi[i][1] = __float_as_uint(a1.x); alo[i][1] = __float_as_uint(a1.y);
                ahi[i][2] = __float_as_uint(a2.x); alo[i][2] = __float_as_uint(a2.y);
                ahi[i][3] = __float_as_uint(a3.x); alo[i][3] = __float_as_uint(a3.y);
            }
#pragma unroll
            for (int j = 0; j < 8; j++) {
                const int nc = nw + j * 8 + g;
                const float2 b0 = Xs[r0][nc];
                const float2 b1 = Xs[r1][nc];
                const unsigned bh0 = __float_as_uint(b0.x), bl0 = __float_as_uint(b0.y);
                const unsigned bh1 = __float_as_uint(b1.x), bl1 = __float_as_uint(b1.y);
#pragma unroll
                for (int i = 0; i < 2; i++) {
                    mma_tf32(c[i][j], ahi[i], bh0, bh1);
                    mma_tf32(c[i][j], alo[i], bh0, bh1);
                    mma_tf32(c[i][j], ahi[i], bl0, bl1);
                }
            }
        }
    }

    const float rs = rsqrtf(1.0f + 1e-5f);
#pragma unroll
    for (int i = 0; i < 2; i++) {
#pragma unroll
        for (int half = 0; half < 2; half++) {
            const int oc = ocw + i * 16 + g + half * 8;
            const float bi = bias  ? bias[oc]       : 0.0f;
            const float sc = gamma ? gamma[oc] * rs : 1.0f;
            const float bb = gamma ? beta[oc]       : 0.0f;
#pragma unroll
            for (int j = 0; j < 8; j++) {
                const int nc = n0 + nw + j * 8 + 2 * t;
                float v0 = fmaf(c[i][j][half * 2]     + bi, sc, bb);
                float v1 = fmaf(c[i][j][half * 2 + 1] + bi, sc, bb);
                if (addB) {
                    const float2 ad = *(const float2*)&addB[(size_t)oc * kN + nc];
                    v0 += ad.x; v1 += ad.y;
                }
                if (relu) { v0 = fmaxf(v0, 0.0f); v1 = fmaxf(v1, 0.0f); }
                *(float2*)&Yb[(size_t)oc * kN + nc] = make_float2(v0, v1);
            }
        }
    }
}

__global__ __launch_bounds__(256, 2) void gemm_mma(
    const float* __restrict__ W, const float* __restrict__ X, float* __restrict__ Y,
    const float* __restrict__ bias, const float* __restrict__ gamma,
    const float* __restrict__ beta, const float* __restrict__ add,
    int OC, int IC, int relu)
{
    __shared__ float2 Ws[16][132];
    __shared__ float2 Xs[16][132];
    const int b   = blockIdx.z;
    const int n0  = blockIdx.x * 128;
    const int oc0 = blockIdx.y * 128;
    gemm_mma_tile(W + (size_t)oc0 * IC,
                  X + (size_t)b * IC * kN,
                  Y + ((size_t)b * OC + oc0) * kN,
                  IC, n0,
                  bias  ? bias  + oc0 : nullptr,
                  gamma ? gamma + oc0 : nullptr,
                  beta  ? beta  + oc0 : nullptr,
                  add   ? add + ((size_t)b * OC + oc0) * kN : nullptr,
                  relu, Ws, Xs);
}

__global__ __launch_bounds__(256, 2) void qkv_mma(
    const float* __restrict__ Wq, const float* __restrict__ Wk, const float* __restrict__ Wv,
    const float* __restrict__ qf, const float* __restrict__ vf,
    float* __restrict__ Q, float* __restrict__ K, float* __restrict__ V)
{
    __shared__ float2 Ws[16][132];
    __shared__ float2 Xs[16][132];
    const int b = blockIdx.z;
    const int y = blockIdx.y;
    const float* W = (y == 0) ? Wq : (y == 1) ? Wk : Wv;
    const float* X = ((y == 0) ? qf : vf) + (size_t)b * kC * kN;
    float*       Y = ((y == 0) ? Q : (y == 1) ? K : V) + (size_t)b * kC * kN;
    gemm_mma_tile(W, X, Y, kC, blockIdx.x * 128,
                  nullptr, nullptr, nullptr, nullptr, 0, Ws, Xs);
}

// ---------------- v_feat helpers ----------------
__global__ void gbias_kernel(const float* __restrict__ fuW, const float* __restrict__ gf,
                             float* __restrict__ gb)
{
    const int b = blockIdx.x, c = threadIdx.x;
    const float* w = fuW + (size_t)c * (3 + kCG) + 3;
    const float* g = gf + b * kCG;
    float s = 0.0f;
    for (int j = 0; j < kCG; j++) s = fmaf(w[j], g[j], s);
    gb[b * kC + c] = s;
}

__global__ void vfeat_kernel(
    const float* __restrict__ fuW, const float* __restrict__ fub,
    const float* __restrict__ fug, const float* __restrict__ fube,
    const float* __restrict__ gb, const float* __restrict__ up_xyz,
    float* __restrict__ vf)
{
    const int b = blockIdx.z, c = blockIdx.y;
    const int n = blockIdx.x * 256 + threadIdx.x;
    const float w0 = fuW[c * (3 + kCG) + 0];
    const float w1 = fuW[c * (3 + kCG) + 1];
    const float w2 = fuW[c * (3 + kCG) + 2];
    const float x = up_xyz[(b * kN + n) * 3 + 0];
    const float y = up_xyz[(b * kN + n) * 3 + 1];
    const float z = up_xyz[(b * kN + n) * 3 + 2];
    float a = gb[b * kC + c] + fub[c] + w0 * x + w1 * y + w2 * z;
    const float rs = rsqrtf(1.0f + 1e-5f);
    a = fmaf(a, fug[c] * rs, fube[c]);
    vf[((size_t)b * kC + c) * kN + n] = fmaxf(a, 0.0f);
}

// ---------------- tf32 MMA flash attention (no max tracking) ----------------
__global__ __launch_bounds__(128) void attn_mma(
    const float* __restrict__ Q, const float* __restrict__ K,
    const float* __restrict__ V, float* __restrict__ O)
{
    __shared__ float Ks[kD][72];
    __shared__ float Vs[kD][72];
    const int bh   = blockIdx.y;
    const int tid  = threadIdx.x;
    const int warp = tid >> 5;
    const int lane = tid & 31;
    const int g    = lane >> 2;
    const int t    = lane & 3;

    const float* Qb = Q + (size_t)bh * kD * kN;
    const float* Kb = K + (size_t)bh * kD * kN;
    const float* Vb = V + (size_t)bh * kD * kN;
    float*       Ob = O + (size_t)bh * kD * kN;

    const float ALPHA = 0.25f * 1.44269504088896340736f;
    const int q0 = blockIdx.x * 64 + warp * 16 + g;

    unsigned aq[2][4];
#pragma unroll
    for (int ks = 0; ks < 2; ks++) {
        aq[ks][0] = cvt_tf32(Qb[(size_t)(ks * 8 + t)     * kN + q0]     * ALPHA);
        aq[ks][1] = cvt_tf32(Qb[(size_t)(ks * 8 + t)     * kN + q0 + 8] * ALPHA);
        aq[ks][2] = cvt_tf32(Qb[(size_t)(ks * 8 + t + 4) * kN + q0]     * ALPHA);
        aq[ks][3] = cvt_tf32(Qb[(size_t)(ks * 8 + t + 4) * kN + q0 + 8] * ALPHA);
    }

    float o0[4] = {0.f, 0.f, 0.f, 0.f};
    float o1[4] = {0.f, 0.f, 0.f, 0.f};
    float l0 = 0.f, l1 = 0.f;

    const int ld_d = tid >> 3;
    const int ld_k = (tid & 7) * 8;

    for (int kt = 0; kt < kN / 64; kt++) {
        const int k0 = kt * 64;
        __syncthreads();
        *(float4*)&Ks[ld_d][ld_k]     = *(const float4*)&Kb[(size_t)ld_d * kN + k0 + ld_k];
        *(float4*)&Ks[ld_d][ld_k + 4] = *(const float4*)&Kb[(size_t)ld_d * kN + k0 + ld_k + 4];
        *(float4*)&Vs[ld_d][ld_k]     = *(const float4*)&Vb[(size_t)ld_d * kN + k0 + ld_k];
        *(float4*)&Vs[ld_d][ld_k + 4] = *(const float4*)&Vb[(size_t)ld_d * kN + k0 + ld_k + 4];
        __syncthreads();

#pragma unroll
        for (int nt = 0; nt < 8; nt++) {
            float c[4] = {0.f, 0.f, 0.f, 0.f};
#pragma unroll
            for (int ks = 0; ks < 2; ks++) {
                const unsigned kb0 = __float_as_uint(Ks[ks * 8 + t][nt * 8 + g]);
                const unsigned kb1 = __float_as_uint(Ks[ks * 8 + t + 4][nt * 8 + g]);
                mma_tf32(c, aq[ks], kb0, kb1);
            }
            const float p0 = ex2(c[0]);
            const float p1 = ex2(c[1]);
            const float p2 = ex2(c[2]);
            const float p3 = ex2(c[3]);
            l0 += p0 + p1;
            l1 += p2 + p3;
            const unsigned pa[4] = {__float_as_uint(p0), __float_as_uint(p2),
                                    __float_as_uint(p1), __float_as_uint(p3)};
#pragma unroll
            for (int dt = 0; dt < 2; dt++) {
                const float2 bv = *(const float2*)&Vs[dt * 8 + g][nt * 8 + 2 * t];
                mma_tf32(dt ? o1 : o0, pa,
                         __float_as_uint(bv.x), __float_as_uint(bv.y));
            }
        }
    }

    l0 += __shfl_xor_sync(0xFFFFFFFFu, l0, 1);
    l0 += __shfl_xor_sync(0xFFFFFFFFu, l0, 2);
    l1 += __shfl_xor_sync(0xFFFFFFFFu, l1, 1);
    l1 += __shfl_xor_sync(0xFFFFFFFFu, l1, 2);
    const float inv0 = 1.0f / l0;
    const float inv1 = 1.0f / l1;

#pragma unroll
    for (int dt = 0; dt < 2; dt++) {
        const float* o = dt ? o1 : o0;
        const int d = dt * 8 + 2 * t;
        Ob[(size_t)d       * kN + q0]     = o[0] * inv0;
        Ob[(size_t)(d + 1) * kN + q0]     = o[1] * inv0;
        Ob[(size_t)d       * kN + q0 + 8] = o[2] * inv1;
        Ob[(size_t)(d + 1) * kN + q0 + 8] = o[3] * inv1;
    }
}

// ---------------- launch ----------------
extern "C" void kernel_launch(void* const* d_in, const int* in_sizes, int n_in,
                              void* d_out, int out_size)
{
    const float* up_xyz   = (const float*)d_in[0];
    const float* xyz      = (const float*)d_in[1];
    const float* features = (const float*)d_in[2];
    const float* gfeat    = (const float*)d_in[3];
    const float* fp1_W = (const float*)d_in[4];
    const float* fp1_b = (const float*)d_in[5];
    const float* fp1_g = (const float*)d_in[6];
    const float* fp1_be= (const float*)d_in[7];
    const float* fp2_W = (const float*)d_in[8];
    const float* fp2_b = (const float*)d_in[9];
    const float* fp2_g = (const float*)d_in[10];
    const float* fp2_be= (const float*)d_in[11];
    const float* qm_W  = (const float*)d_in[12];
    const float* qm_b  = (const float*)d_in[13];
    const float* qm_g  = (const float*)d_in[14];
    const float* qm_be = (const float*)d_in[15];
    const float* fu_W  = (const float*)d_in[16];
    const float* fu_b  = (const float*)d_in[17];
    const float* fu_g  = (const float*)d_in[18];
    const float* fu_be = (const float*)d_in[19];
    const float* Wq    = (const float*)d_in[20];
    const float* Wk    = (const float*)d_in[21];
    const float* Wv    = (const float*)d_in[22];
    const float* Wp    = (const float*)d_in[23];
    const float* bp    = (const float*)d_in[24];
    const float* om_W  = (const float*)d_in[25];
    const float* om_b  = (const float*)d_in[26];
    const float* om_g  = (const float*)d_in[27];
    const float* om_be = (const float*)d_in[28];

    float *interp, *h1, *nf, *qf, *vf, *Q, *K, *V, *O, *y, *gb, *w;
    int* idx;
    cudaGetSymbolAddress((void**)&interp, g_interp);
    cudaGetSymbolAddress((void**)&h1,     g_h1);
    cudaGetSymbolAddress((void**)&nf,     g_nf);
    cudaGetSymbolAddress((void**)&qf,     g_qf);
    cudaGetSymbolAddress((void**)&vf,     g_vf);
    cudaGetSymbolAddress((void**)&Q,      g_Q);
    cudaGetSymbolAddress((void**)&K,      g_K);
    cudaGetSymbolAddress((void**)&V,      g_V);
    cudaGetSymbolAddress((void**)&O,      g_O);
    cudaGetSymbolAddress((void**)&y,      g_y);
    cudaGetSymbolAddress((void**)&gb,     g_gb);
    cudaGetSymbolAddress((void**)&idx,    g_idx);
    cudaGetSymbolAddress((void**)&w,      g_w);

    // 1) three_nn + weights
    knn_kernel<<<dim3(kN / 128, kB), 128>>>(up_xyz, xyz, idx, w);
    // 2) inverse-distance interpolation -> (B,256,N)
    interp_kernel<<<dim3(kN / 256, kCIN, kB), 256>>>(features, idx, w, interp);
    // 3) fp mlp: CBL 256->256, CBL 256->128  (3xTF32 tensor GEMM)
    gemm_mma<<<dim3(kN / 128, kCIN / 128, kB), 256>>>(fp1_W, interp, h1,
                                                      fp1_b, fp1_g, fp1_be, nullptr, kCIN, kCIN, 1);
    gemm_mma<<<dim3(kN / 128, 1, kB), 256>>>(fp2_W, h1, nf,
                                             fp2_b, fp2_g, fp2_be, nullptr, kCFP, kCIN, 1);
    // 4) q_feat = CBL 128->128
    gemm_mma<<<dim3(kN / 128, 1, kB), 256>>>(qm_W, nf, qf,
                                             qm_b, qm_g, qm_be, nullptr, kC, kCFP, 1);
    // 5) v_feat via collapsed global-feature bias
    gbias_kernel<<<kB, kC>>>(fu_W, gfeat, gb);
    vfeat_kernel<<<dim3(kN / 256, kC, kB), 256>>>(fu_W, fu_b, fu_g, fu_be, gb, up_xyz, vf);
    // 6) fused Q/K/V projections
    qkv_mma<<<dim3(kN / 128, 3, kB), 256>>>(Wq, Wk, Wv, qf, vf, Q, K, V);
    // 7) attention (tf32 tensor-core flash, no-max softmax)
    attn_mma<<<dim3(kN / 64, kB * kH), 128>>>(Q, K, V, O);
    // 8) proj + residual add (y = qf + Wp@O + bp)
    gemm_mma<<<dim3(kN / 128, 1, kB), 256>>>(Wp, O, y, bp, nullptr, nullptr, qf, kC, kC, 0);
    // 9) out = CBL(y)
    gemm_mma<<<dim3(kN / 128, 1, kB), 256>>>(om_W, y, (float*)d_out,
                                             om_b, om_g, om_be, nullptr, kC, kC, 1);
}